// round 9
// baseline (speedup 1.0000x reference)
#include <cuda_runtime.h>
#include <math.h>

#define TN     512
#define TRANGE 8.0f                              // table covers x0 in [-8, 8)
#define TSCALE ((float)TN / (2.0f * TRANGE))     // 32
#define TOFFS  ((float)(TN / 2))                 // 256

#define RPC     256                              // rows per chunk (= blockDim)
#define FPC     (RPC * 18)                       // floats per chunk = 4608
#define F4PC    (FPC / 4)                        // float4 per chunk = 1152
#define XPITCH  257                              // padded row pitch (words)

// Constant weights (prescaled): [0:4) w_ih' [4:8) w_hh' [8:12) bias'
// (i,f,o gates scaled by 0.5 to fold into sigmoid; g unscaled)
// [12:30) w_lin  [30] b_lin
__constant__ float c_w[31];

__device__ float  g_stage[31];
__device__ float4 g_tab[TN];   // (h0, c0, dh, dc) as function of x0

__device__ __forceinline__ float tanh_fast(float x) {
    float y;
    asm("tanh.approx.f32 %0, %1;" : "=f"(y) : "f"(x));
    return y;
}
// argument already prescaled by 0.5
__device__ __forceinline__ float sigmoid_pre(float half_x) {
    return fmaf(tanh_fast(half_x), 0.5f, 0.5f);
}

// ---------------- setup: stage weights + build exact step0 table -----------
__device__ __forceinline__ void step0_exact(
    float x, float wi, float wg, float wo, float bi, float bg, float bo,
    float* h0, float* c0)
{
    float i0 = 1.0f / (1.0f + expf(-(fmaf(wi, x, bi))));
    float g0 = tanhf(fmaf(wg, x, bg));
    float o0 = 1.0f / (1.0f + expf(-(fmaf(wo, x, bo))));
    float c  = i0 * g0;
    *c0 = c;
    *h0 = o0 * tanhf(c);
}

__global__ void setup_kernel(const float* __restrict__ w_ih,
                             const float* __restrict__ w_hh,
                             const float* __restrict__ b_ih,
                             const float* __restrict__ b_hh,
                             const float* __restrict__ w_lin,
                             const float* __restrict__ b_lin)
{
    int t = threadIdx.x;
    if (t < 4) {
        float s = (t == 2) ? 1.0f : 0.5f;       // g gate unscaled
        g_stage[t]     = w_ih[t] * s;
        g_stage[4 + t] = w_hh[t] * s;
        g_stage[8 + t] = (b_ih[t] + b_hh[t]) * s;
    } else if (t < 22) {
        g_stage[8 + t] = w_lin[t - 4];          // 12..29
    } else if (t == 22) {
        g_stage[30] = b_lin[0];
    }

    const float wi = w_ih[0], wg = w_ih[2], wo = w_ih[3];
    const float bi = b_ih[0] + b_hh[0];
    const float bg = b_ih[2] + b_hh[2];
    const float bo = b_ih[3] + b_hh[3];
    const float inv = 1.0f / TSCALE;

    for (int i = t; i < TN; i += blockDim.x) {
        float x0 = ((float)i       - TOFFS) * inv;
        float x1 = ((float)(i + 1) - TOFFS) * inv;
        float h0, c0, h1, c1;
        step0_exact(x0, wi, wg, wo, bi, bg, bo, &h0, &c0);
        step0_exact(x1, wi, wg, wo, bi, bg, bo, &h1, &c1);
        g_tab[i] = make_float4(h0, c0, h1 - h0, c1 - c0);
    }
}

// One LSTM-element (3 steps) + linear accumulation. Step 0 via smem table.
#define ELEM(ACC, X0, X1, X2, WI)                                             \
    do {                                                                      \
        float t_ = fmaf((X0), TSCALE, TOFFS);                                 \
        t_ = fminf(fmaxf(t_, 0.0f), (float)TN - 0.51f);                       \
        int   i_  = (int)t_;                                                  \
        float dx_ = t_ - (float)i_;                                           \
        float4 e4_ = stab[i_];                                                \
        float h_ = fmaf(dx_, e4_.z, e4_.x);                                   \
        float c_ = fmaf(dx_, e4_.w, e4_.y);                                   \
        ACC = fmaf(h_, c_w[(WI)], ACC);                                       \
        float i1_ = sigmoid_pre(fmaf(c_w[4], h_, fmaf(c_w[0], (X1), c_w[8])));\
        float f1_ = sigmoid_pre(fmaf(c_w[5], h_, fmaf(c_w[1], (X1), c_w[9])));\
        float g1_ = tanh_fast  (fmaf(c_w[6], h_, fmaf(c_w[2], (X1), c_w[10])));\
        float o1_ = sigmoid_pre(fmaf(c_w[7], h_, fmaf(c_w[3], (X1), c_w[11])));\
        c_ = fmaf(f1_, c_, i1_ * g1_);                                        \
        h_ = o1_ * tanh_fast(c_);                                             \
        ACC = fmaf(h_, c_w[(WI) + 1], ACC);                                   \
        float i2_ = sigmoid_pre(fmaf(c_w[4], h_, fmaf(c_w[0], (X2), c_w[8])));\
        float f2_ = sigmoid_pre(fmaf(c_w[5], h_, fmaf(c_w[1], (X2), c_w[9])));\
        float g2_ = tanh_fast  (fmaf(c_w[6], h_, fmaf(c_w[2], (X2), c_w[10])));\
        float o2_ = sigmoid_pre(fmaf(c_w[7], h_, fmaf(c_w[3], (X2), c_w[11])));\
        c_ = fmaf(f2_, c_, i2_ * g2_);                                        \
        h_ = o2_ * tanh_fast(c_);                                             \
        ACC = fmaf(h_, c_w[(WI) + 2], ACC);                                   \
    } while (0)

// ---------------- main kernel: smem-staged, transposed chunk ---------------
__global__ __launch_bounds__(256) void lstm_lin_kernel(
    const float* __restrict__ x, float* __restrict__ out, int nchunks)
{
    __shared__ float4 stab[TN];             // 8 KB
    __shared__ float  xs[18 * XPITCH];      // 18.5 KB, xs[col*XPITCH + row]

    stab[threadIdx.x]       = __ldg(&g_tab[threadIdx.x]);
    stab[threadIdx.x + 256] = __ldg(&g_tab[threadIdx.x + 256]);

    const int l = threadIdx.x;

    for (int ch = blockIdx.x; ch < nchunks; ch += gridDim.x) {
        __syncthreads();   // xs free to overwrite (also orders table fill on iter 0)

        // coalesced load of 256 rows (4608 floats = 1152 float4), transpose-scatter
        const float4* src = reinterpret_cast<const float4*>(x) + (size_t)ch * F4PC;
        for (int i = l; i < F4PC; i += 256) {
            float4 d = __ldg(src + i);
            int f = 4 * i;
            int r0 = f / 18,       c0 = f - r0 * 18;
            int r1 = (f + 1) / 18, c1 = (f + 1) - r1 * 18;
            int r2 = (f + 2) / 18, c2 = (f + 2) - r2 * 18;
            int r3 = (f + 3) / 18, c3 = (f + 3) - r3 * 18;
            xs[c0 * XPITCH + r0] = d.x;
            xs[c1 * XPITCH + r1] = d.y;
            xs[c2 * XPITCH + r2] = d.z;
            xs[c3 * XPITCH + r3] = d.w;
        }
        __syncthreads();

        float acc = c_w[30];
        // element e uses columns 3e..3e+2; reads are conflict-free (pitch 257)
        ELEM(acc, xs[ 0 * XPITCH + l], xs[ 1 * XPITCH + l], xs[ 2 * XPITCH + l], 12);
        ELEM(acc, xs[ 3 * XPITCH + l], xs[ 4 * XPITCH + l], xs[ 5 * XPITCH + l], 15);
        ELEM(acc, xs[ 6 * XPITCH + l], xs[ 7 * XPITCH + l], xs[ 8 * XPITCH + l], 18);
        ELEM(acc, xs[ 9 * XPITCH + l], xs[10 * XPITCH + l], xs[11 * XPITCH + l], 21);
        ELEM(acc, xs[12 * XPITCH + l], xs[13 * XPITCH + l], xs[14 * XPITCH + l], 24);
        ELEM(acc, xs[15 * XPITCH + l], xs[16 * XPITCH + l], xs[17 * XPITCH + l], 27);

        out[ch * RPC + l] = acc;
    }
}

extern "C" void kernel_launch(void* const* d_in, const int* in_sizes, int n_in,
                              void* d_out, int out_size)
{
    // Inputs: x, w_ih, w_hh, b_ih, b_hh, w_lin, b_lin
    const float* x = (const float*)d_in[0];

    setup_kernel<<<1, 256>>>((const float*)d_in[1], (const float*)d_in[2],
                             (const float*)d_in[3], (const float*)d_in[4],
                             (const float*)d_in[5], (const float*)d_in[6]);

    void* stage_ptr = nullptr;
    cudaGetSymbolAddress(&stage_ptr, g_stage);
    cudaMemcpyToSymbolAsync(c_w, stage_ptr, 31 * sizeof(float), 0,
                            cudaMemcpyDeviceToDevice, 0);

    int nchunks = out_size / RPC;   // 8192 chunks of 256 rows
    lstm_lin_kernel<<<1184, 256>>>(x, (float*)d_out, nchunks);
}

// round 10
// speedup vs baseline: 1.2823x; 1.2823x over previous
#include <cuda_runtime.h>
#include <math.h>

#define TN     512
#define TRANGE 8.0f                              // table covers x0 in [-8, 8)
#define TSCALE ((float)TN / (2.0f * TRANGE))     // 32
#define TOFFS  ((float)(TN / 2))                 // 256

#define RPC    256                               // rows per chunk (= blockDim)
#define F4PC   (RPC * 18 / 4)                    // float4 per chunk = 1152

// Constant weights (prescaled): [0:4) w_ih' [4:8) w_hh' [8:12) bias'
// (i,f,o gates scaled by 0.5 to fold into sigmoid; g unscaled)
// [12:30) w_lin  [30] b_lin
__constant__ float c_w[31];

__device__ float  g_stage[31];
__device__ float4 g_tab[TN];   // (h0, c0, dh, dc) as function of x0

__device__ __forceinline__ float tanh_fast(float x) {
    float y;
    asm("tanh.approx.f32 %0, %1;" : "=f"(y) : "f"(x));
    return y;
}
// argument already prescaled by 0.5
__device__ __forceinline__ float sigmoid_pre(float half_x) {
    return fmaf(tanh_fast(half_x), 0.5f, 0.5f);
}

// ---------------- setup: stage weights + build exact step0 table -----------
__device__ __forceinline__ void step0_exact(
    float x, float wi, float wg, float wo, float bi, float bg, float bo,
    float* h0, float* c0)
{
    float i0 = 1.0f / (1.0f + expf(-(fmaf(wi, x, bi))));
    float g0 = tanhf(fmaf(wg, x, bg));
    float o0 = 1.0f / (1.0f + expf(-(fmaf(wo, x, bo))));
    float c  = i0 * g0;
    *c0 = c;
    *h0 = o0 * tanhf(c);
}

__global__ void setup_kernel(const float* __restrict__ w_ih,
                             const float* __restrict__ w_hh,
                             const float* __restrict__ b_ih,
                             const float* __restrict__ b_hh,
                             const float* __restrict__ w_lin,
                             const float* __restrict__ b_lin)
{
    int t = threadIdx.x;
    if (t < 4) {
        float s = (t == 2) ? 1.0f : 0.5f;       // g gate unscaled
        g_stage[t]     = w_ih[t] * s;
        g_stage[4 + t] = w_hh[t] * s;
        g_stage[8 + t] = (b_ih[t] + b_hh[t]) * s;
    } else if (t < 22) {
        g_stage[8 + t] = w_lin[t - 4];          // 12..29
    } else if (t == 22) {
        g_stage[30] = b_lin[0];
    }

    const float wi = w_ih[0], wg = w_ih[2], wo = w_ih[3];
    const float bi = b_ih[0] + b_hh[0];
    const float bg = b_ih[2] + b_hh[2];
    const float bo = b_ih[3] + b_hh[3];
    const float inv = 1.0f / TSCALE;

    for (int i = t; i < TN; i += blockDim.x) {
        float x0 = ((float)i       - TOFFS) * inv;
        float x1 = ((float)(i + 1) - TOFFS) * inv;
        float h0, c0, h1, c1;
        step0_exact(x0, wi, wg, wo, bi, bg, bo, &h0, &c0);
        step0_exact(x1, wi, wg, wo, bi, bg, bo, &h1, &c1);
        g_tab[i] = make_float4(h0, c0, h1 - h0, c1 - c0);
    }
}

// One LSTM-element (3 steps) + linear accumulation. Step 0 via smem table.
#define ELEM(ACC, X0, X1, X2, WI)                                             \
    do {                                                                      \
        float t_ = fmaf((X0), TSCALE, TOFFS);                                 \
        t_ = fminf(fmaxf(t_, 0.0f), (float)TN - 0.51f);                       \
        int   i_  = (int)t_;                                                  \
        float dx_ = t_ - (float)i_;                                           \
        float4 e4_ = stab[i_];                                                \
        float h_ = fmaf(dx_, e4_.z, e4_.x);                                   \
        float c_ = fmaf(dx_, e4_.w, e4_.y);                                   \
        ACC = fmaf(h_, c_w[(WI)], ACC);                                       \
        float i1_ = sigmoid_pre(fmaf(c_w[4], h_, fmaf(c_w[0], (X1), c_w[8])));\
        float f1_ = sigmoid_pre(fmaf(c_w[5], h_, fmaf(c_w[1], (X1), c_w[9])));\
        float g1_ = tanh_fast  (fmaf(c_w[6], h_, fmaf(c_w[2], (X1), c_w[10])));\
        float o1_ = sigmoid_pre(fmaf(c_w[7], h_, fmaf(c_w[3], (X1), c_w[11])));\
        c_ = fmaf(f1_, c_, i1_ * g1_);                                        \
        h_ = o1_ * tanh_fast(c_);                                             \
        ACC = fmaf(h_, c_w[(WI) + 1], ACC);                                   \
        float i2_ = sigmoid_pre(fmaf(c_w[4], h_, fmaf(c_w[0], (X2), c_w[8])));\
        float f2_ = sigmoid_pre(fmaf(c_w[5], h_, fmaf(c_w[1], (X2), c_w[9])));\
        float g2_ = tanh_fast  (fmaf(c_w[6], h_, fmaf(c_w[2], (X2), c_w[10])));\
        float o2_ = sigmoid_pre(fmaf(c_w[7], h_, fmaf(c_w[3], (X2), c_w[11])));\
        c_ = fmaf(f2_, c_, i2_ * g2_);                                        \
        h_ = o2_ * tanh_fast(c_);                                             \
        ACC = fmaf(h_, c_w[(WI) + 2], ACC);                                   \
    } while (0)

// ---------------- main kernel: one 256-row chunk per CTA -------------------
__global__ __launch_bounds__(256) void lstm_lin_kernel(
    const float* __restrict__ x, float* __restrict__ out)
{
    __shared__ float4 stab[TN];          // 8 KB step-0 table
    __shared__ float  xs[RPC * 18];      // 18 KB input chunk, linear layout

    const int tid = threadIdx.x;

    // table fill (coalesced, L2-hot)
    stab[tid]       = __ldg(&g_tab[tid]);
    stab[tid + 256] = __ldg(&g_tab[tid + 256]);

    // chunk load: fully coalesced float4, linear conflict-free STS.128
    {
        const float4* src = reinterpret_cast<const float4*>(x)
                          + (size_t)blockIdx.x * F4PC;
        float4* xs4 = reinterpret_cast<float4*>(xs);
#pragma unroll
        for (int k = 0; k < 4; k++)
            xs4[tid + 256 * k] = __ldg(src + tid + 256 * k);
        if (tid < F4PC - 1024)
            xs4[tid + 1024] = __ldg(src + tid + 1024);
    }
    __syncthreads();

    // compute: thread tid owns row tid of the chunk (18 floats, smem-resident)
    const float* row = xs + tid * 18;

    float acc = c_w[30];
    ELEM(acc, row[ 0], row[ 1], row[ 2], 12);
    ELEM(acc, row[ 3], row[ 4], row[ 5], 15);
    ELEM(acc, row[ 6], row[ 7], row[ 8], 18);
    ELEM(acc, row[ 9], row[10], row[11], 21);
    ELEM(acc, row[12], row[13], row[14], 24);
    ELEM(acc, row[15], row[16], row[17], 27);

    out[blockIdx.x * RPC + tid] = acc;
}

extern "C" void kernel_launch(void* const* d_in, const int* in_sizes, int n_in,
                              void* d_out, int out_size)
{
    // Inputs: x, w_ih, w_hh, b_ih, b_hh, w_lin, b_lin
    const float* x = (const float*)d_in[0];

    setup_kernel<<<1, 256>>>((const float*)d_in[1], (const float*)d_in[2],
                             (const float*)d_in[3], (const float*)d_in[4],
                             (const float*)d_in[5], (const float*)d_in[6]);

    void* stage_ptr = nullptr;
    cudaGetSymbolAddress(&stage_ptr, g_stage);
    cudaMemcpyToSymbolAsync(c_w, stage_ptr, 31 * sizeof(float), 0,
                            cudaMemcpyDeviceToDevice, 0);

    int nchunks = out_size / RPC;   // 8192 CTAs, one chunk each
    lstm_lin_kernel<<<nchunks, 256>>>(x, (float*)d_out);
}